// round 15
// baseline (speedup 1.0000x reference)
#include <cuda_runtime.h>
#include <cuda_fp16.h>
#include <math_constants.h>
#include <cstdint>

#define NH    16
#define HD    64
#define SEQ   1024
#define BATCH 4
#define HID   1024

// fp16 scratch
__device__ __half g_Qh[BATCH * NH * SEQ * HD];
__device__ __half g_Kh[BATCH * NH * SEQ * HD];
__device__ __half g_Vt[BATCH * NH * HD * SEQ];
__device__ __half g_HSh[BATCH * SEQ * HID];
__device__ __half g_Wh[3 * HID * HID];
__device__ __half emb_h[2047 * HD];

__device__ __forceinline__ uint32_t h2u(float x, float y) {
    __half2 h = __floats2half2_rn(x, y);
    return *(uint32_t*)&h;
}

__device__ __forceinline__ void mma16n8k16h(float c[4], const uint32_t a[4],
                                            const uint32_t b[2]) {
    asm volatile(
        "mma.sync.aligned.m16n8k16.row.col.f32.f16.f16.f32 "
        "{%0,%1,%2,%3}, {%4,%5,%6,%7}, {%8,%9}, {%0,%1,%2,%3};"
        : "+f"(c[0]), "+f"(c[1]), "+f"(c[2]), "+f"(c[3])
        : "r"(a[0]), "r"(a[1]), "r"(a[2]), "r"(a[3]), "r"(b[0]), "r"(b[1]));
}

// ===========================================================================
// Kernel 0: one-time fp32 -> fp16 conversion of hs, w, dist_emb
// ===========================================================================
#define HSQ (BATCH * SEQ * HID / 4)
#define WQ  (3 * HID * HID / 4)
#define EQ  (2047 * HD / 4)

__global__ void cvt_all(const float* __restrict__ hs,
                        const float* __restrict__ w,
                        const float* __restrict__ emb)
{
    const size_t i4 = (size_t)blockIdx.x * 256 + threadIdx.x;
    const float* src; __half* dst; size_t off;
    if (i4 < HSQ)            { src = hs;  dst = g_HSh; off = i4; }
    else if (i4 < HSQ + WQ)  { src = w;   dst = g_Wh;  off = i4 - HSQ; }
    else if (i4 < HSQ + WQ + EQ) { src = emb; dst = emb_h; off = i4 - HSQ - WQ; }
    else return;
    const float4 v = *(const float4*)(src + off * 4);
    *(uint2*)(dst + off * 4) = make_uint2(h2u(v.x, v.y), h2u(v.z, v.w));
}

// ===========================================================================
// Kernel 1: fused QKV projection, fp16 in / fp16 mma / fp16 out (V transposed)
// (unchanged from R14)
// ===========================================================================
#define SSTH 40
#define QH_TILE (128 * SSTH)
#define QG_SMEM_B (4 * QH_TILE * 2)

__global__ __launch_bounds__(256) void qkv_gemm_mma(
    const float* __restrict__ bias)
{
    extern __shared__ __align__(16) __half smh[];
    __half* As = smh;
    __half* Bs = smh + 2 * QH_TILE;

    const int tid  = threadIdx.x;
    const int m0   = blockIdx.y * 128;
    const int n0   = blockIdx.x * 128;
    const int lrow = tid >> 3;
    const int lc4  = tid & 7;

    const int lane = tid & 31, g = lane >> 2, t = lane & 3;
    const int wid  = tid >> 5, wm = wid >> 2, wn = wid & 3;

    uint2 ra[4], rb[4];

#pragma unroll
    for (int it = 0; it < 4; ++it) {
        const int row = lrow + it * 32;
        ra[it] = *(const uint2*)(g_HSh + (size_t)(m0 + row) * HID + lc4 * 4);
        rb[it] = *(const uint2*)(g_Wh  + (size_t)(n0 + row) * HID + lc4 * 4);
    }
#pragma unroll
    for (int it = 0; it < 4; ++it) {
        const int row = lrow + it * 32;
        *(uint2*)&As[row * SSTH + lc4 * 4] = ra[it];
        *(uint2*)&Bs[row * SSTH + lc4 * 4] = rb[it];
    }
    __syncthreads();

    float c[4][4][4];
#pragma unroll
    for (int mi = 0; mi < 4; ++mi)
#pragma unroll
        for (int ni = 0; ni < 4; ++ni)
#pragma unroll
            for (int r = 0; r < 4; ++r) c[mi][ni][r] = 0.f;

    for (int ch = 0; ch < 32; ++ch) {
        const int p = ch & 1;
        if (ch < 31) {
            const int k0 = (ch + 1) * 32;
#pragma unroll
            for (int it = 0; it < 4; ++it) {
                const int row = lrow + it * 32;
                ra[it] = *(const uint2*)(g_HSh + (size_t)(m0 + row) * HID + k0 + lc4 * 4);
                rb[it] = *(const uint2*)(g_Wh  + (size_t)(n0 + row) * HID + k0 + lc4 * 4);
            }
        }

        const __half* Ab = As + p * QH_TILE;
        const __half* Bb = Bs + p * QH_TILE;
#pragma unroll
        for (int ks = 0; ks < 2; ++ks) {
            const int kc = ks * 16 + 2 * t;
            uint32_t a[4][4], b[4][2];
#pragma unroll
            for (int mi = 0; mi < 4; ++mi) {
                const __half* ap = Ab + (wm * 64 + mi * 16 + g) * SSTH + kc;
                a[mi][0] = *(const uint32_t*)(ap);
                a[mi][1] = *(const uint32_t*)(ap + 8 * SSTH);
                a[mi][2] = *(const uint32_t*)(ap + 8);
                a[mi][3] = *(const uint32_t*)(ap + 8 * SSTH + 8);
            }
#pragma unroll
            for (int ni = 0; ni < 4; ++ni) {
                const __half* bp = Bb + (wn * 32 + ni * 8 + g) * SSTH + kc;
                b[ni][0] = *(const uint32_t*)(bp);
                b[ni][1] = *(const uint32_t*)(bp + 8);
            }
#pragma unroll
            for (int mi = 0; mi < 4; ++mi)
#pragma unroll
                for (int ni = 0; ni < 4; ++ni)
                    mma16n8k16h(c[mi][ni], a[mi], b[ni]);
        }

        if (ch < 31) {
            __half* An = As + ((ch + 1) & 1) * QH_TILE;
            __half* Bn = Bs + ((ch + 1) & 1) * QH_TILE;
#pragma unroll
            for (int it = 0; it < 4; ++it) {
                const int row = lrow + it * 32;
                *(uint2*)&An[row * SSTH + lc4 * 4] = ra[it];
                *(uint2*)&Bn[row * SSTH + lc4 * 4] = rb[it];
            }
        }
        __syncthreads();
    }

    const int tsel = n0 >> 10;
    if (tsel < 2) {
        __half* dst = (tsel == 0) ? g_Qh : g_Kh;
#pragma unroll
        for (int mi = 0; mi < 4; ++mi) {
            const int m  = m0 + wm * 64 + mi * 16 + g;
            const int bb = m >> 10;
            const int s  = m & 1023;
#pragma unroll
            for (int ni = 0; ni < 4; ++ni) {
                const int gn  = n0 + wn * 32 + ni * 8 + t * 2;
                const int rem = gn & 1023;
                const int hh  = rem >> 6;
                const int dd  = rem & 63;
                const float2 bi = *(const float2*)(bias + gn);
                __half* base = dst + ((size_t)(bb * NH + hh) * SEQ + s) * HD + dd;
                *(uint32_t*)(base) = h2u(c[mi][ni][0] + bi.x, c[mi][ni][1] + bi.y);
                *(uint32_t*)(base + 8 * HD) = h2u(c[mi][ni][2] + bi.x, c[mi][ni][3] + bi.y);
            }
        }
    } else {
#pragma unroll
        for (int mi = 0; mi < 4; ++mi) {
            const int m  = m0 + wm * 64 + mi * 16 + g;
            const int bb = m >> 10;
            const int s  = m & 1023;
#pragma unroll
            for (int ni = 0; ni < 4; ++ni) {
                const int gn  = n0 + wn * 32 + ni * 8 + t * 2;
                const int rem = gn & 1023;
                const int hh  = rem >> 6;
                const int dd  = rem & 63;
                const float2 bi = *(const float2*)(bias + gn);
                __half* base = g_Vt + ((size_t)(bb * NH + hh) * HD + dd) * SEQ + s;
                base[0]       = __float2half(c[mi][ni][0] + bi.x);
                base[SEQ]     = __float2half(c[mi][ni][1] + bi.y);
                base[8]       = __float2half(c[mi][ni][2] + bi.x);
                base[SEQ + 8] = __float2half(c[mi][ni][3] + bi.y);
            }
        }
    }
}

// ===========================================================================
// Kernel 2: attention, balanced pair-split warps + 3 blocks/SM.
// Each warp: 16-row strip x 32-col half of S. All 8 warps do band GEMM,
// QK, gather, softmax (pair-combined via smem pmax/psum), P store, V copy, PV.
// ===========================================================================
#define AT_SMEM_B 72960

__global__ __launch_bounds__(256, 3) void attn_mma(
    const float* __restrict__ mask,
    float* __restrict__ out)
{
    extern __shared__ __align__(16) float sm2[];
    __half* Qh    = (__half*)sm2;             // [64][72]
    __half* Kh    = (__half*)(sm2 + 2304);    // [64][72] (Vth alias)
    __half* Vth   = Kh;
    __half* Eh    = (__half*)(sm2 + 4608);    // [128][72] (Ph alias [64][72])
    __half* Ph    = Eh;
    __half* QEh   = (__half*)(sm2 + 9216);    // [64][136]
    __half* KEh   = (__half*)(sm2 + 13568);   // [64][136]
    float*  pmax  = sm2 + 17920;              // [2][64]
    float*  psum  = sm2 + 18048;              // [2][64]
    float*  maskS = sm2 + 18176;              // [64]

    const int tid  = threadIdx.x;
    const int lane = tid & 31, g = lane >> 2, t = lane & 3;
    const int wid  = tid >> 5;
    const int ms   = (wid & 3) * 16;          // 16-row strip
    const int wn2  = wid >> 2;                // pair half (0/1)
    const int nqk  = wn2 * 32;                // this warp's 32-col half
    const bool isA = (wid < 4);
    const int bh = blockIdx.y, b = bh >> 4, hh = bh & 15;
    const int l0 = blockIdx.x * 64;
    const int iA = ms + g, iB = ms + g + 8;

    // ---- stage Q (raw fp16 copy) ----
    const __half* Qg = g_Qh + ((size_t)bh * SEQ + l0) * HD;
#pragma unroll
    for (int it = 0; it < 2; ++it) {
        const int cidx = tid + it * 256;
        const int row = cidx >> 3, c16 = cidx & 7;
        *(uint4*)&Qh[row * 72 + c16 * 8] = *(const uint4*)(Qg + row * 64 + c16 * 8);
    }

    float mrow0 = -CUDART_INF_F, mrow1 = -CUDART_INF_F;
    float lsum0 = 0.f, lsum1 = 0.f;
    float acc[4][4];
#pragma unroll
    for (int nt = 0; nt < 4; ++nt)
#pragma unroll
        for (int r = 0; r < 4; ++r) acc[nt][r] = 0.f;

    float S[4][4];
    const int ebase = isA ? ms : (48 - ms);   // band start col for QE / KE

    for (int r0 = 0; r0 < SEQ; r0 += 64) {
        const int gb_ = l0 - r0 + 960;

        __syncthreads();   // sync1: prior PV reads (Ph, Vth) done
        const __half* Kg = g_Kh + ((size_t)bh * SEQ + r0) * HD;
#pragma unroll
        for (int it = 0; it < 2; ++it) {
            const int cidx = tid + it * 256;
            const int row = cidx >> 3, c16 = cidx & 7;
            *(uint4*)&Kh[row * 72 + c16 * 8] = *(const uint4*)(Kg + row * 64 + c16 * 8);
        }
#pragma unroll
        for (int it = 0; it < 4; ++it) {
            const int cidx = tid + it * 256;
            const int row = cidx >> 3, c16 = cidx & 7;
            const int er = min(gb_ + row, 2046);
            *(uint4*)&Eh[row * 72 + c16 * 8] = *(const uint4*)(emb_h + er * 64 + c16 * 8);
        }
        if (tid < 16)
            *(float4*)&maskS[tid * 4] = *(const float4*)(mask + b * SEQ + r0 + tid * 4);
        __syncthreads();   // sync2: operands ready

        // ---- fp16 band GEMM: QE (warps 0-3) / KE (warps 4-7), 10 n8 tiles ----
        {
            const __half* Ah = isA ? Qh : Kh;
            __half* dstT = isA ? QEh : KEh;
#pragma unroll
            for (int c5 = 0; c5 < 2; ++c5) {
                float qe[5][4];
#pragma unroll
                for (int nt = 0; nt < 5; ++nt)
#pragma unroll
                    for (int r = 0; r < 4; ++r) qe[nt][r] = 0.f;
#pragma unroll
                for (int ks = 0; ks < 4; ++ks) {
                    const int kc = ks * 16 + 2 * t;
                    uint32_t a[4];
                    const __half* ap = Ah + (ms + g) * 72 + kc;
                    a[0] = *(const uint32_t*)(ap);
                    a[1] = *(const uint32_t*)(ap + 8 * 72);
                    a[2] = *(const uint32_t*)(ap + 8);
                    a[3] = *(const uint32_t*)(ap + 8 * 72 + 8);
#pragma unroll
                    for (int nt = 0; nt < 5; ++nt) {
                        const int col = ebase + (c5 * 5 + nt) * 8;
                        const __half* bp = Eh + (col + g) * 72 + kc;
                        uint32_t bb[2] = {*(const uint32_t*)(bp),
                                          *(const uint32_t*)(bp + 8)};
                        mma16n8k16h(qe[nt], a, bb);
                    }
                }
#pragma unroll
                for (int nt = 0; nt < 5; ++nt) {
                    const int col = ebase + (c5 * 5 + nt) * 8 + 2 * t;
                    *(__half2*)&dstT[(ms + g) * 136 + col] =
                        __floats2half2_rn(qe[nt][0], qe[nt][1]);
                    *(__half2*)&dstT[(ms + g + 8) * 136 + col] =
                        __floats2half2_rn(qe[nt][2], qe[nt][3]);
                }
            }
        }
        // ---- QK (all 8 warps, 16-row strip x 32-col half) ----
#pragma unroll
        for (int nt = 0; nt < 4; ++nt)
#pragma unroll
            for (int r = 0; r < 4; ++r) S[nt][r] = 0.f;
#pragma unroll
        for (int ks = 0; ks < 4; ++ks) {
            const int kc = ks * 16 + 2 * t;
            uint32_t a[4];
            const __half* ap = Qh + (ms + g) * 72 + kc;
            a[0] = *(const uint32_t*)(ap);
            a[1] = *(const uint32_t*)(ap + 8 * 72);
            a[2] = *(const uint32_t*)(ap + 8);
            a[3] = *(const uint32_t*)(ap + 8 * 72 + 8);
#pragma unroll
            for (int nt = 0; nt < 4; ++nt) {
                const __half* bp = Kh + (nqk + nt * 8 + g) * 72 + kc;
                uint32_t bb[2] = {*(const uint32_t*)(bp),
                                  *(const uint32_t*)(bp + 8)};
                mma16n8k16h(S[nt], a, bb);
            }
        }
        __syncthreads();   // sync3: QEh/KEh done; Kh/Eh mma reads done

        // ---- V prefetch (LDG early, STS later; Vth aliases Kh now free) ----
        uint4 vpre[2];
        {
            const __half* Vg = g_Vt + (size_t)bh * HD * SEQ + r0;
#pragma unroll
            for (int it = 0; it < 2; ++it) {
                const int cidx = tid + it * 256;
                const int dd = cidx >> 3, c16 = cidx & 7;
                vpre[it] = *(const uint4*)(Vg + (size_t)dd * SEQ + c16 * 8);
            }
        }

        // ---- gather + scale + mask; intra-warp partials ----
        float rmax0 = -CUDART_INF_F, rmax1 = -CUDART_INF_F;
#pragma unroll
        for (int nt = 0; nt < 4; ++nt) {
            const int j0 = nqk + nt * 8 + 2 * t, j1 = j0 + 1;
            const float mk0 = maskS[j0], mk1 = maskS[j1];
            const int bA0 = iA - j0 + 63, bA1 = iA - j1 + 63;
            const int bB0 = iB - j0 + 63, bB1 = iB - j1 + 63;
            S[nt][0] = (S[nt][0] + __half2float(QEh[iA * 136 + bA0])
                                 + __half2float(KEh[j0 * 136 + bA0])) * 0.125f + mk0;
            S[nt][1] = (S[nt][1] + __half2float(QEh[iA * 136 + bA1])
                                 + __half2float(KEh[j1 * 136 + bA1])) * 0.125f + mk1;
            S[nt][2] = (S[nt][2] + __half2float(QEh[iB * 136 + bB0])
                                 + __half2float(KEh[j0 * 136 + bB0])) * 0.125f + mk0;
            S[nt][3] = (S[nt][3] + __half2float(QEh[iB * 136 + bB1])
                                 + __half2float(KEh[j1 * 136 + bB1])) * 0.125f + mk1;
            rmax0 = fmaxf(rmax0, fmaxf(S[nt][0], S[nt][1]));
            rmax1 = fmaxf(rmax1, fmaxf(S[nt][2], S[nt][3]));
        }
        rmax0 = fmaxf(rmax0, __shfl_xor_sync(0xffffffffu, rmax0, 1));
        rmax0 = fmaxf(rmax0, __shfl_xor_sync(0xffffffffu, rmax0, 2));
        rmax1 = fmaxf(rmax1, __shfl_xor_sync(0xffffffffu, rmax1, 1));
        rmax1 = fmaxf(rmax1, __shfl_xor_sync(0xffffffffu, rmax1, 2));
        if (t == 0) { pmax[wn2 * 64 + iA] = rmax0; pmax[wn2 * 64 + iB] = rmax1; }
        __syncthreads();   // syncE1: pmax exchange

        const float pm0 = fmaxf(pmax[iA], pmax[64 + iA]);
        const float pm1 = fmaxf(pmax[iB], pmax[64 + iB]);
        const float mn0 = fmaxf(mrow0, pm0), mn1 = fmaxf(mrow1, pm1);
        const float c0 = __expf(mrow0 - mn0), c1 = __expf(mrow1 - mn1);
        mrow0 = mn0; mrow1 = mn1;
        float ps0 = 0.f, ps1 = 0.f;
#pragma unroll
        for (int nt = 0; nt < 4; ++nt) {
            S[nt][0] = __expf(S[nt][0] - mn0); ps0 += S[nt][0];
            S[nt][1] = __expf(S[nt][1] - mn0); ps0 += S[nt][1];
            S[nt][2] = __expf(S[nt][2] - mn1); ps1 += S[nt][2];
            S[nt][3] = __expf(S[nt][3] - mn1); ps1 += S[nt][3];
        }
        ps0 += __shfl_xor_sync(0xffffffffu, ps0, 1);
        ps0 += __shfl_xor_sync(0xffffffffu, ps0, 2);
        ps1 += __shfl_xor_sync(0xffffffffu, ps1, 1);
        ps1 += __shfl_xor_sync(0xffffffffu, ps1, 2);
        if (t == 0) { psum[wn2 * 64 + iA] = ps0; psum[wn2 * 64 + iB] = ps1; }

        // ---- P store (fp16, this warp's 32-col half) + V STS ----
#pragma unroll
        for (int nt = 0; nt < 4; ++nt) {
            const int col = nqk + nt * 8 + 2 * t;
            *(__half2*)&Ph[iA * 72 + col] = __floats2half2_rn(S[nt][0], S[nt][1]);
            *(__half2*)&Ph[iB * 72 + col] = __floats2half2_rn(S[nt][2], S[nt][3]);
        }
#pragma unroll
        for (int it = 0; it < 2; ++it) {
            const int cidx = tid + it * 256;
            const int dd = cidx >> 3, c16 = cidx & 7;
            *(uint4*)&Vth[dd * 72 + c16 * 8] = vpre[it];
        }
        __syncthreads();   // sync4: Ph, Vth, psum ready

        lsum0 = lsum0 * c0 + psum[iA] + psum[64 + iA];
        lsum1 = lsum1 * c1 + psum[iB] + psum[64 + iB];

        // ---- PV (fp16): strip ms x col-half nqk ----
#pragma unroll
        for (int nt = 0; nt < 4; ++nt) {
            acc[nt][0] *= c0; acc[nt][1] *= c0;
            acc[nt][2] *= c1; acc[nt][3] *= c1;
        }
#pragma unroll
        for (int ks = 0; ks < 4; ++ks) {
            const int kc = ks * 16 + 2 * t;
            uint32_t a[4];
            const __half* ap = Ph + (ms + g) * 72 + kc;
            a[0] = *(const uint32_t*)(ap);
            a[1] = *(const uint32_t*)(ap + 8 * 72);
            a[2] = *(const uint32_t*)(ap + 8);
            a[3] = *(const uint32_t*)(ap + 8 * 72 + 8);
#pragma unroll
            for (int nt = 0; nt < 4; ++nt) {
                const __half* bp = Vth + (nqk + nt * 8 + g) * 72 + kc;
                uint32_t bb[2] = {*(const uint32_t*)(bp),
                                  *(const uint32_t*)(bp + 8)};
                mma16n8k16h(acc[nt], a, bb);
            }
        }
    }

    // ---- write context: each warp owns rows iA/iB, its 32-col half ----
    {
        const float inv0 = 1.f / lsum0;
        const float inv1 = 1.f / lsum1;
        const int row0 = l0 + iA, row1 = l0 + iB;
#pragma unroll
        for (int nt = 0; nt < 4; ++nt) {
            const int col = hh * HD + nqk + nt * 8 + 2 * t;
            *(float2*)(out + (size_t)(b * SEQ + row0) * HID + col) =
                make_float2(acc[nt][0] * inv0, acc[nt][1] * inv0);
            *(float2*)(out + (size_t)(b * SEQ + row1) * HID + col) =
                make_float2(acc[nt][2] * inv1, acc[nt][3] * inv1);
        }
    }
}

// ---------------------------------------------------------------------------
extern "C" void kernel_launch(void* const* d_in, const int* in_sizes, int n_in,
                              void* d_out, int out_size)
{
    (void)in_sizes; (void)n_in; (void)out_size;
    const float* hs   = (const float*)d_in[0];
    const float* w    = (const float*)d_in[1];
    const float* bias = (const float*)d_in[2];
    const float* emb  = (const float*)d_in[3];
    const float* mask = (const float*)d_in[4];
    float* out = (float*)d_out;

    const int total_q = HSQ + WQ + EQ;
    cvt_all<<<(total_q + 255) / 256, 256>>>(hs, w, emb);

    cudaFuncSetAttribute(qkv_gemm_mma,
                         cudaFuncAttributeMaxDynamicSharedMemorySize, QG_SMEM_B);
    qkv_gemm_mma<<<dim3(HID * 3 / 128, BATCH * SEQ / 128), 256, QG_SMEM_B>>>(bias);

    cudaFuncSetAttribute(attn_mma,
                         cudaFuncAttributeMaxDynamicSharedMemorySize, AT_SMEM_B);
    attn_mma<<<dim3(SEQ / 64, BATCH * NH), 256, AT_SMEM_B>>>(mask, out);
}

// round 16
// speedup vs baseline: 1.0350x; 1.0350x over previous
#include <cuda_runtime.h>
#include <cuda_fp16.h>
#include <math_constants.h>
#include <cstdint>

#define NH    16
#define HD    64
#define SEQ   1024
#define BATCH 4
#define HID   1024

// fp16 scratch
__device__ __half g_Qh[BATCH * NH * SEQ * HD];
__device__ __half g_Kh[BATCH * NH * SEQ * HD];
__device__ __half g_Vt[BATCH * NH * HD * SEQ];
__device__ __half g_HSh[BATCH * SEQ * HID];
__device__ __half g_Wh[3 * HID * HID];
__device__ __half emb_h[2047 * HD];

__device__ __forceinline__ uint32_t h2u(float x, float y) {
    __half2 h = __floats2half2_rn(x, y);
    return *(uint32_t*)&h;
}

__device__ __forceinline__ void mma16n8k16h(float c[4], const uint32_t a[4],
                                            const uint32_t b[2]) {
    asm volatile(
        "mma.sync.aligned.m16n8k16.row.col.f32.f16.f16.f32 "
        "{%0,%1,%2,%3}, {%4,%5,%6,%7}, {%8,%9}, {%0,%1,%2,%3};"
        : "+f"(c[0]), "+f"(c[1]), "+f"(c[2]), "+f"(c[3])
        : "r"(a[0]), "r"(a[1]), "r"(a[2]), "r"(a[3]), "r"(b[0]), "r"(b[1]));
}

__device__ __forceinline__ void ldsm4(uint32_t* r, uint32_t addr) {
    asm volatile("ldmatrix.sync.aligned.m8n8.x4.shared.b16 {%0,%1,%2,%3}, [%4];"
        : "=r"(r[0]), "=r"(r[1]), "=r"(r[2]), "=r"(r[3]) : "r"(addr));
}

// ===========================================================================
// Kernel 0: one-time fp32 -> fp16 conversion of hs, w, dist_emb
// ===========================================================================
#define HSQ (BATCH * SEQ * HID / 4)
#define WQ  (3 * HID * HID / 4)
#define EQ  (2047 * HD / 4)

__global__ void cvt_all(const float* __restrict__ hs,
                        const float* __restrict__ w,
                        const float* __restrict__ emb)
{
    const size_t i4 = (size_t)blockIdx.x * 256 + threadIdx.x;
    const float* src; __half* dst; size_t off;
    if (i4 < HSQ)            { src = hs;  dst = g_HSh; off = i4; }
    else if (i4 < HSQ + WQ)  { src = w;   dst = g_Wh;  off = i4 - HSQ; }
    else if (i4 < HSQ + WQ + EQ) { src = emb; dst = emb_h; off = i4 - HSQ - WQ; }
    else return;
    const float4 v = *(const float4*)(src + off * 4);
    *(uint2*)(dst + off * 4) = make_uint2(h2u(v.x, v.y), h2u(v.z, v.w));
}

// ===========================================================================
// Kernel 1: fused QKV projection, fp16; fragment loads via ldmatrix.x4
// ===========================================================================
#define SSTH 40
#define QH_TILE (128 * SSTH)
#define QG_SMEM_B (4 * QH_TILE * 2)

__global__ __launch_bounds__(256) void qkv_gemm_mma(
    const float* __restrict__ bias)
{
    extern __shared__ __align__(16) __half smh[];
    __half* As = smh;
    __half* Bs = smh + 2 * QH_TILE;

    const int tid  = threadIdx.x;
    const int m0   = blockIdx.y * 128;
    const int n0   = blockIdx.x * 128;
    const int lrow = tid >> 3;
    const int lc4  = tid & 7;

    const int lane = tid & 31, g = lane >> 2, t = lane & 3;
    const int wid  = tid >> 5, wm = wid >> 2, wn = wid & 3;

    // ldmatrix lane-address components
    const uint32_t sb = (uint32_t)__cvta_generic_to_shared(smh);
    const int arow  = wm * 64 + (lane & 15);      // + mi*16
    const int akoff = (lane >> 4) * 8;            // k-half select
    const int bn    = wn * 32 + (lane >> 4) * 8 + (lane & 7);  // + nip*16
    const int bkoff = ((lane >> 3) & 1) * 8;

    uint2 ra[4], rb[4];

#pragma unroll
    for (int it = 0; it < 4; ++it) {
        const int row = lrow + it * 32;
        ra[it] = *(const uint2*)(g_HSh + (size_t)(m0 + row) * HID + lc4 * 4);
        rb[it] = *(const uint2*)(g_Wh  + (size_t)(n0 + row) * HID + lc4 * 4);
    }
#pragma unroll
    for (int it = 0; it < 4; ++it) {
        const int row = lrow + it * 32;
        *(uint2*)&As[row * SSTH + lc4 * 4] = ra[it];
        *(uint2*)&Bs[row * SSTH + lc4 * 4] = rb[it];
    }
    __syncthreads();

    float c[4][4][4];
#pragma unroll
    for (int mi = 0; mi < 4; ++mi)
#pragma unroll
        for (int ni = 0; ni < 4; ++ni)
#pragma unroll
            for (int r = 0; r < 4; ++r) c[mi][ni][r] = 0.f;

    for (int ch = 0; ch < 32; ++ch) {
        const int p = ch & 1;
        if (ch < 31) {
            const int k0 = (ch + 1) * 32;
#pragma unroll
            for (int it = 0; it < 4; ++it) {
                const int row = lrow + it * 32;
                ra[it] = *(const uint2*)(g_HSh + (size_t)(m0 + row) * HID + k0 + lc4 * 4);
                rb[it] = *(const uint2*)(g_Wh  + (size_t)(n0 + row) * HID + k0 + lc4 * 4);
            }
        }

        const uint32_t aB = sb + (uint32_t)(p * QH_TILE) * 2;
        const uint32_t bB = sb + (uint32_t)((2 + p) * QH_TILE) * 2;
#pragma unroll
        for (int ks = 0; ks < 2; ++ks) {
            uint32_t a[4][4], b[4][2];
#pragma unroll
            for (int mi = 0; mi < 4; ++mi)
                ldsm4(a[mi], aB + (uint32_t)(((arow + mi * 16) * SSTH) + ks * 16 + akoff) * 2);
#pragma unroll
            for (int nip = 0; nip < 2; ++nip) {
                uint32_t r[4];
                ldsm4(r, bB + (uint32_t)(((bn + nip * 16) * SSTH) + ks * 16 + bkoff) * 2);
                b[2 * nip][0] = r[0]; b[2 * nip][1] = r[1];
                b[2 * nip + 1][0] = r[2]; b[2 * nip + 1][1] = r[3];
            }
#pragma unroll
            for (int mi = 0; mi < 4; ++mi)
#pragma unroll
                for (int ni = 0; ni < 4; ++ni)
                    mma16n8k16h(c[mi][ni], a[mi], b[ni]);
        }

        if (ch < 31) {
            __half* An = As + ((ch + 1) & 1) * QH_TILE;
            __half* Bn = Bs + ((ch + 1) & 1) * QH_TILE;
#pragma unroll
            for (int it = 0; it < 4; ++it) {
                const int row = lrow + it * 32;
                *(uint2*)&An[row * SSTH + lc4 * 4] = ra[it];
                *(uint2*)&Bn[row * SSTH + lc4 * 4] = rb[it];
            }
        }
        __syncthreads();
    }

    const int tsel = n0 >> 10;
    if (tsel < 2) {
        __half* dst = (tsel == 0) ? g_Qh : g_Kh;
#pragma unroll
        for (int mi = 0; mi < 4; ++mi) {
            const int m  = m0 + wm * 64 + mi * 16 + g;
            const int bb = m >> 10;
            const int s  = m & 1023;
#pragma unroll
            for (int ni = 0; ni < 4; ++ni) {
                const int gn  = n0 + wn * 32 + ni * 8 + t * 2;
                const int rem = gn & 1023;
                const int hh  = rem >> 6;
                const int dd  = rem & 63;
                const float2 bi = *(const float2*)(bias + gn);
                __half* base = dst + ((size_t)(bb * NH + hh) * SEQ + s) * HD + dd;
                *(uint32_t*)(base) = h2u(c[mi][ni][0] + bi.x, c[mi][ni][1] + bi.y);
                *(uint32_t*)(base + 8 * HD) = h2u(c[mi][ni][2] + bi.x, c[mi][ni][3] + bi.y);
            }
        }
    } else {
#pragma unroll
        for (int mi = 0; mi < 4; ++mi) {
            const int m  = m0 + wm * 64 + mi * 16 + g;
            const int bb = m >> 10;
            const int s  = m & 1023;
#pragma unroll
            for (int ni = 0; ni < 4; ++ni) {
                const int gn  = n0 + wn * 32 + ni * 8 + t * 2;
                const int rem = gn & 1023;
                const int hh  = rem >> 6;
                const int dd  = rem & 63;
                const float2 bi = *(const float2*)(bias + gn);
                __half* base = g_Vt + ((size_t)(bb * NH + hh) * HD + dd) * SEQ + s;
                base[0]       = __float2half(c[mi][ni][0] + bi.x);
                base[SEQ]     = __float2half(c[mi][ni][1] + bi.y);
                base[8]       = __float2half(c[mi][ni][2] + bi.x);
                base[SEQ + 8] = __float2half(c[mi][ni][3] + bi.y);
            }
        }
    }
}

// ===========================================================================
// Kernel 2: attention (R14 version — proven best, untouched)
// ===========================================================================
#define AT_SMEM_B 72448

__global__ __launch_bounds__(256, 2) void attn_mma(
    const float* __restrict__ mask,
    float* __restrict__ out)
{
    extern __shared__ __align__(16) float sm2[];
    __half* Qh    = (__half*)sm2;             // [64][72]
    __half* Kh    = (__half*)(sm2 + 2304);    // [64][72] (Vth alias)
    __half* Vth   = Kh;
    __half* Eh    = (__half*)(sm2 + 4608);    // [128][72] (Ph alias [64][72])
    __half* Ph    = Eh;
    __half* QEh   = (__half*)(sm2 + 9216);    // [64][136]
    __half* KEh   = (__half*)(sm2 + 13568);   // [64][136]
    float*  corrs = sm2 + 17920;              // [64]
    float*  lsums = sm2 + 17984;              // [64]
    float*  maskS = sm2 + 18048;              // [64]

    const int tid  = threadIdx.x;
    const int lane = tid & 31, g = lane >> 2, t = lane & 3;
    const int wid  = tid >> 5;
    const int ms   = (wid & 3) * 16;          // 16-row strip
    const int nh   = (wid >> 2) * 32;         // n-half for PV
    const bool isA = (wid < 4);
    const int bh = blockIdx.y, b = bh >> 4, hh = bh & 15;
    const int l0 = blockIdx.x * 64;

    // ---- stage Q (raw fp16 copy) ----
    const __half* Qg = g_Qh + ((size_t)bh * SEQ + l0) * HD;
#pragma unroll
    for (int it = 0; it < 2; ++it) {
        const int cidx = tid + it * 256;
        const int row = cidx >> 3, c16 = cidx & 7;
        *(uint4*)&Qh[row * 72 + c16 * 8] = *(const uint4*)(Qg + row * 64 + c16 * 8);
    }

    float mrow0 = -CUDART_INF_F, mrow1 = -CUDART_INF_F;
    float lsum0 = 0.f, lsum1 = 0.f;
    float acc[4][4];
#pragma unroll
    for (int nt = 0; nt < 4; ++nt)
#pragma unroll
        for (int r = 0; r < 4; ++r) acc[nt][r] = 0.f;

    float S[8][4];
    const int ebase = isA ? ms : (48 - ms);   // band start col for QE / KE

    for (int r0 = 0; r0 < SEQ; r0 += 64) {
        const int gb_ = l0 - r0 + 960;

        __syncthreads();   // sync1: prior PV reads (Ph, Vth) done
        const __half* Kg = g_Kh + ((size_t)bh * SEQ + r0) * HD;
#pragma unroll
        for (int it = 0; it < 2; ++it) {
            const int cidx = tid + it * 256;
            const int row = cidx >> 3, c16 = cidx & 7;
            *(uint4*)&Kh[row * 72 + c16 * 8] = *(const uint4*)(Kg + row * 64 + c16 * 8);
        }
#pragma unroll
        for (int it = 0; it < 4; ++it) {
            const int cidx = tid + it * 256;
            const int row = cidx >> 3, c16 = cidx & 7;
            const int er = min(gb_ + row, 2046);
            *(uint4*)&Eh[row * 72 + c16 * 8] = *(const uint4*)(emb_h + er * 64 + c16 * 8);
        }
        if (tid < 16)
            *(float4*)&maskS[tid * 4] = *(const float4*)(mask + b * SEQ + r0 + tid * 4);
        __syncthreads();   // sync2: operands ready

        // ---- fp16 band GEMM: QE (A warps) / KE (B warps), 10 n8 tiles ----
        {
            const __half* Ah = isA ? Qh : Kh;
            __half* dstT = isA ? QEh : KEh;
#pragma unroll
            for (int c5 = 0; c5 < 2; ++c5) {
                float qe[5][4];
#pragma unroll
                for (int nt = 0; nt < 5; ++nt)
#pragma unroll
                    for (int r = 0; r < 4; ++r) qe[nt][r] = 0.f;
#pragma unroll
                for (int ks = 0; ks < 4; ++ks) {
                    const int kc = ks * 16 + 2 * t;
                    uint32_t a[4];
                    const __half* ap = Ah + (ms + g) * 72 + kc;
                    a[0] = *(const uint32_t*)(ap);
                    a[1] = *(const uint32_t*)(ap + 8 * 72);
                    a[2] = *(const uint32_t*)(ap + 8);
                    a[3] = *(const uint32_t*)(ap + 8 * 72 + 8);
#pragma unroll
                    for (int nt = 0; nt < 5; ++nt) {
                        const int col = ebase + (c5 * 5 + nt) * 8;
                        const __half* bp = Eh + (col + g) * 72 + kc;
                        uint32_t bb[2] = {*(const uint32_t*)(bp),
                                          *(const uint32_t*)(bp + 8)};
                        mma16n8k16h(qe[nt], a, bb);
                    }
                }
#pragma unroll
                for (int nt = 0; nt < 5; ++nt) {
                    const int col = ebase + (c5 * 5 + nt) * 8 + 2 * t;
                    *(__half2*)&dstT[(ms + g) * 136 + col] =
                        __floats2half2_rn(qe[nt][0], qe[nt][1]);
                    *(__half2*)&dstT[(ms + g + 8) * 136 + col] =
                        __floats2half2_rn(qe[nt][2], qe[nt][3]);
                }
            }
        }
        if (isA) {
            // ---- QK (fp16, k=16) ----
#pragma unroll
            for (int nt = 0; nt < 8; ++nt)
#pragma unroll
                for (int r = 0; r < 4; ++r) S[nt][r] = 0.f;
#pragma unroll
            for (int ks = 0; ks < 4; ++ks) {
                const int kc = ks * 16 + 2 * t;
                uint32_t a[4];
                const __half* ap = Qh + (ms + g) * 72 + kc;
                a[0] = *(const uint32_t*)(ap);
                a[1] = *(const uint32_t*)(ap + 8 * 72);
                a[2] = *(const uint32_t*)(ap + 8);
                a[3] = *(const uint32_t*)(ap + 8 * 72 + 8);
#pragma unroll
                for (int nt = 0; nt < 8; ++nt) {
                    const __half* bp = Kh + (nt * 8 + g) * 72 + kc;
                    uint32_t bb[2] = {*(const uint32_t*)(bp),
                                      *(const uint32_t*)(bp + 8)};
                    mma16n8k16h(S[nt], a, bb);
                }
            }
        }
        __syncthreads();   // sync3: QEh/KEh done; Kh/Eh mma reads done

        if (isA) {
            // ---- gather + scale + mask + online softmax + P store (fp16) ----
            const int iA = ms + g, iB = ms + g + 8;
            float rmax0 = -CUDART_INF_F, rmax1 = -CUDART_INF_F;
#pragma unroll
            for (int nt = 0; nt < 8; ++nt) {
                const int j0 = nt * 8 + 2 * t, j1 = j0 + 1;
                const float mk0 = maskS[j0], mk1 = maskS[j1];
                const int bA0 = iA - j0 + 63, bA1 = iA - j1 + 63;
                const int bB0 = iB - j0 + 63, bB1 = iB - j1 + 63;
                S[nt][0] = (S[nt][0] + __half2float(QEh[iA * 136 + bA0])
                                     + __half2float(KEh[j0 * 136 + bA0])) * 0.125f + mk0;
                S[nt][1] = (S[nt][1] + __half2float(QEh[iA * 136 + bA1])
                                     + __half2float(KEh[j1 * 136 + bA1])) * 0.125f + mk1;
                S[nt][2] = (S[nt][2] + __half2float(QEh[iB * 136 + bB0])
                                     + __half2float(KEh[j0 * 136 + bB0])) * 0.125f + mk0;
                S[nt][3] = (S[nt][3] + __half2float(QEh[iB * 136 + bB1])
                                     + __half2float(KEh[j1 * 136 + bB1])) * 0.125f + mk1;
                rmax0 = fmaxf(rmax0, fmaxf(S[nt][0], S[nt][1]));
                rmax1 = fmaxf(rmax1, fmaxf(S[nt][2], S[nt][3]));
            }
            rmax0 = fmaxf(rmax0, __shfl_xor_sync(0xffffffffu, rmax0, 1));
            rmax0 = fmaxf(rmax0, __shfl_xor_sync(0xffffffffu, rmax0, 2));
            rmax1 = fmaxf(rmax1, __shfl_xor_sync(0xffffffffu, rmax1, 1));
            rmax1 = fmaxf(rmax1, __shfl_xor_sync(0xffffffffu, rmax1, 2));
            const float mn0 = fmaxf(mrow0, rmax0), mn1 = fmaxf(mrow1, rmax1);
            const float c0 = __expf(mrow0 - mn0), c1 = __expf(mrow1 - mn1);
            mrow0 = mn0; mrow1 = mn1;
            float ps0 = 0.f, ps1 = 0.f;
#pragma unroll
            for (int nt = 0; nt < 8; ++nt) {
                S[nt][0] = __expf(S[nt][0] - mn0); ps0 += S[nt][0];
                S[nt][1] = __expf(S[nt][1] - mn0); ps0 += S[nt][1];
                S[nt][2] = __expf(S[nt][2] - mn1); ps1 += S[nt][2];
                S[nt][3] = __expf(S[nt][3] - mn1); ps1 += S[nt][3];
            }
            ps0 += __shfl_xor_sync(0xffffffffu, ps0, 1);
            ps0 += __shfl_xor_sync(0xffffffffu, ps0, 2);
            ps1 += __shfl_xor_sync(0xffffffffu, ps1, 1);
            ps1 += __shfl_xor_sync(0xffffffffu, ps1, 2);
            lsum0 = lsum0 * c0 + ps0;
            lsum1 = lsum1 * c1 + ps1;
            if (t == 0) { corrs[iA] = c0; corrs[iB] = c1; }
#pragma unroll
            for (int nt = 0; nt < 8; ++nt) {
                const int col = nt * 8 + 2 * t;
                *(__half2*)&Ph[iA * 72 + col] = __floats2half2_rn(S[nt][0], S[nt][1]);
                *(__half2*)&Ph[iB * 72 + col] = __floats2half2_rn(S[nt][2], S[nt][3]);
            }
        } else {
            // ---- B warps: copy pre-transposed V tile ----
            const __half* Vg = g_Vt + (size_t)bh * HD * SEQ + r0;
            const int tl = tid - 128;
#pragma unroll
            for (int it = 0; it < 4; ++it) {
                const int cidx = tl + it * 128;
                const int dd = cidx >> 3, c16 = cidx & 7;
                *(uint4*)&Vth[dd * 72 + c16 * 8] =
                    *(const uint4*)(Vg + (size_t)dd * SEQ + c16 * 8);
            }
        }
        __syncthreads();   // sync4: Ph, Vth, corrs ready

        // ---- PV (fp16): all warps ----
        {
            const float cc0 = corrs[ms + g], cc1 = corrs[ms + g + 8];
#pragma unroll
            for (int nt = 0; nt < 4; ++nt) {
                acc[nt][0] *= cc0; acc[nt][1] *= cc0;
                acc[nt][2] *= cc1; acc[nt][3] *= cc1;
            }
#pragma unroll
            for (int ks = 0; ks < 4; ++ks) {
                const int kc = ks * 16 + 2 * t;
                uint32_t a[4];
                const __half* ap = Ph + (ms + g) * 72 + kc;
                a[0] = *(const uint32_t*)(ap);
                a[1] = *(const uint32_t*)(ap + 8 * 72);
                a[2] = *(const uint32_t*)(ap + 8);
                a[3] = *(const uint32_t*)(ap + 8 * 72 + 8);
#pragma unroll
                for (int nt = 0; nt < 4; ++nt) {
                    const __half* bp = Vth + (nh + nt * 8 + g) * 72 + kc;
                    uint32_t bb[2] = {*(const uint32_t*)(bp),
                                      *(const uint32_t*)(bp + 8)};
                    mma16n8k16h(acc[nt], a, bb);
                }
            }
        }
    }

    if (isA && t == 0) { lsums[ms + g] = lsum0; lsums[ms + g + 8] = lsum1; }
    __syncthreads();

    {
        const float inv0 = 1.f / lsums[ms + g];
        const float inv1 = 1.f / lsums[ms + g + 8];
        const int row0 = l0 + ms + g, row1 = row0 + 8;
#pragma unroll
        for (int nt = 0; nt < 4; ++nt) {
            const int col = hh * HD + nh + nt * 8 + 2 * t;
            *(float2*)(out + (size_t)(b * SEQ + row0) * HID + col) =
                make_float2(acc[nt][0] * inv0, acc[nt][1] * inv0);
            *(float2*)(out + (size_t)(b * SEQ + row1) * HID + col) =
                make_float2(acc[nt][2] * inv1, acc[nt][3] * inv1);
        }
    }
}

// ---------------------------------------------------------------------------
extern "C" void kernel_launch(void* const* d_in, const int* in_sizes, int n_in,
                              void* d_out, int out_size)
{
    (void)in_sizes; (void)n_in; (void)out_size;
    const float* hs   = (const float*)d_in[0];
    const float* w    = (const float*)d_in[1];
    const float* bias = (const float*)d_in[2];
    const float* emb  = (const float*)d_in[3];
    const float* mask = (const float*)d_in[4];
    float* out = (float*)d_out;

    const int total_q = HSQ + WQ + EQ;
    cvt_all<<<(total_q + 255) / 256, 256>>>(hs, w, emb);

    cudaFuncSetAttribute(qkv_gemm_mma,
                         cudaFuncAttributeMaxDynamicSharedMemorySize, QG_SMEM_B);
    qkv_gemm_mma<<<dim3(HID * 3 / 128, BATCH * SEQ / 128), 256, QG_SMEM_B>>>(bias);

    cudaFuncSetAttribute(attn_mma,
                         cudaFuncAttributeMaxDynamicSharedMemorySize, AT_SMEM_B);
    attn_mma<<<dim3(SEQ / 64, BATCH * NH), 256, AT_SMEM_B>>>(mask, out);
}

// round 17
// speedup vs baseline: 1.0562x; 1.0206x over previous
#include <cuda_runtime.h>
#include <cuda_fp16.h>
#include <math_constants.h>
#include <cstdint>

#define NH    16
#define HD    64
#define SEQ   1024
#define BATCH 4
#define HID   1024

// fp16 scratch
__device__ __half g_Qh[BATCH * NH * SEQ * HD];
__device__ __half g_Kh[BATCH * NH * SEQ * HD];
__device__ __half g_Vt[BATCH * NH * HD * SEQ];
__device__ __half g_HSh[BATCH * SEQ * HID];
__device__ __half g_Wh[3 * HID * HID];
__device__ __half emb_h[2047 * HD];

__device__ __forceinline__ uint32_t h2u(float x, float y) {
    __half2 h = __floats2half2_rn(x, y);
    return *(uint32_t*)&h;
}

__device__ __forceinline__ void mma16n8k16h(float c[4], const uint32_t a[4],
                                            const uint32_t b[2]) {
    asm volatile(
        "mma.sync.aligned.m16n8k16.row.col.f32.f16.f16.f32 "
        "{%0,%1,%2,%3}, {%4,%5,%6,%7}, {%8,%9}, {%0,%1,%2,%3};"
        : "+f"(c[0]), "+f"(c[1]), "+f"(c[2]), "+f"(c[3])
        : "r"(a[0]), "r"(a[1]), "r"(a[2]), "r"(a[3]), "r"(b[0]), "r"(b[1]));
}

__device__ __forceinline__ void ldsm4(uint32_t* r, uint32_t addr) {
    asm volatile("ldmatrix.sync.aligned.m8n8.x4.shared.b16 {%0,%1,%2,%3}, [%4];"
        : "=r"(r[0]), "=r"(r[1]), "=r"(r[2]), "=r"(r[3]) : "r"(addr));
}
__device__ __forceinline__ void ldsm2(uint32_t* r, uint32_t addr) {
    asm volatile("ldmatrix.sync.aligned.m8n8.x2.shared.b16 {%0,%1}, [%2];"
        : "=r"(r[0]), "=r"(r[1]) : "r"(addr));
}

// ===========================================================================
// Kernel 0: one-time fp32 -> fp16 conversion of hs, w, dist_emb
// ===========================================================================
#define HSQ (BATCH * SEQ * HID / 4)
#define WQ  (3 * HID * HID / 4)
#define EQ  (2047 * HD / 4)

__global__ void cvt_all(const float* __restrict__ hs,
                        const float* __restrict__ w,
                        const float* __restrict__ emb)
{
    const size_t i4 = (size_t)blockIdx.x * 256 + threadIdx.x;
    const float* src; __half* dst; size_t off;
    if (i4 < HSQ)            { src = hs;  dst = g_HSh; off = i4; }
    else if (i4 < HSQ + WQ)  { src = w;   dst = g_Wh;  off = i4 - HSQ; }
    else if (i4 < HSQ + WQ + EQ) { src = emb; dst = emb_h; off = i4 - HSQ - WQ; }
    else return;
    const float4 v = *(const float4*)(src + off * 4);
    *(uint2*)(dst + off * 4) = make_uint2(h2u(v.x, v.y), h2u(v.z, v.w));
}

// ===========================================================================
// Kernel 1: fused QKV projection, fp16, ldmatrix fragments (R16 — WIN)
// ===========================================================================
#define SSTH 40
#define QH_TILE (128 * SSTH)
#define QG_SMEM_B (4 * QH_TILE * 2)

__global__ __launch_bounds__(256) void qkv_gemm_mma(
    const float* __restrict__ bias)
{
    extern __shared__ __align__(16) __half smh[];
    __half* As = smh;
    __half* Bs = smh + 2 * QH_TILE;

    const int tid  = threadIdx.x;
    const int m0   = blockIdx.y * 128;
    const int n0   = blockIdx.x * 128;
    const int lrow = tid >> 3;
    const int lc4  = tid & 7;

    const int lane = tid & 31, g = lane >> 2, t = lane & 3;
    const int wid  = tid >> 5, wm = wid >> 2, wn = wid & 3;

    const uint32_t sb = (uint32_t)__cvta_generic_to_shared(smh);
    const int arow  = wm * 64 + (lane & 15);
    const int akoff = (lane >> 4) * 8;
    const int bn    = wn * 32 + (lane >> 4) * 8 + (lane & 7);
    const int bkoff = ((lane >> 3) & 1) * 8;

    uint2 ra[4], rb[4];

#pragma unroll
    for (int it = 0; it < 4; ++it) {
        const int row = lrow + it * 32;
        ra[it] = *(const uint2*)(g_HSh + (size_t)(m0 + row) * HID + lc4 * 4);
        rb[it] = *(const uint2*)(g_Wh  + (size_t)(n0 + row) * HID + lc4 * 4);
    }
#pragma unroll
    for (int it = 0; it < 4; ++it) {
        const int row = lrow + it * 32;
        *(uint2*)&As[row * SSTH + lc4 * 4] = ra[it];
        *(uint2*)&Bs[row * SSTH + lc4 * 4] = rb[it];
    }
    __syncthreads();

    float c[4][4][4];
#pragma unroll
    for (int mi = 0; mi < 4; ++mi)
#pragma unroll
        for (int ni = 0; ni < 4; ++ni)
#pragma unroll
            for (int r = 0; r < 4; ++r) c[mi][ni][r] = 0.f;

    for (int ch = 0; ch < 32; ++ch) {
        const int p = ch & 1;
        if (ch < 31) {
            const int k0 = (ch + 1) * 32;
#pragma unroll
            for (int it = 0; it < 4; ++it) {
                const int row = lrow + it * 32;
                ra[it] = *(const uint2*)(g_HSh + (size_t)(m0 + row) * HID + k0 + lc4 * 4);
                rb[it] = *(const uint2*)(g_Wh  + (size_t)(n0 + row) * HID + k0 + lc4 * 4);
            }
        }

        const uint32_t aB = sb + (uint32_t)(p * QH_TILE) * 2;
        const uint32_t bB = sb + (uint32_t)((2 + p) * QH_TILE) * 2;
#pragma unroll
        for (int ks = 0; ks < 2; ++ks) {
            uint32_t a[4][4], b[4][2];
#pragma unroll
            for (int mi = 0; mi < 4; ++mi)
                ldsm4(a[mi], aB + (uint32_t)(((arow + mi * 16) * SSTH) + ks * 16 + akoff) * 2);
#pragma unroll
            for (int nip = 0; nip < 2; ++nip) {
                uint32_t r[4];
                ldsm4(r, bB + (uint32_t)(((bn + nip * 16) * SSTH) + ks * 16 + bkoff) * 2);
                b[2 * nip][0] = r[0]; b[2 * nip][1] = r[1];
                b[2 * nip + 1][0] = r[2]; b[2 * nip + 1][1] = r[3];
            }
#pragma unroll
            for (int mi = 0; mi < 4; ++mi)
#pragma unroll
                for (int ni = 0; ni < 4; ++ni)
                    mma16n8k16h(c[mi][ni], a[mi], b[ni]);
        }

        if (ch < 31) {
            __half* An = As + ((ch + 1) & 1) * QH_TILE;
            __half* Bn = Bs + ((ch + 1) & 1) * QH_TILE;
#pragma unroll
            for (int it = 0; it < 4; ++it) {
                const int row = lrow + it * 32;
                *(uint2*)&An[row * SSTH + lc4 * 4] = ra[it];
                *(uint2*)&Bn[row * SSTH + lc4 * 4] = rb[it];
            }
        }
        __syncthreads();
    }

    const int tsel = n0 >> 10;
    if (tsel < 2) {
        __half* dst = (tsel == 0) ? g_Qh : g_Kh;
#pragma unroll
        for (int mi = 0; mi < 4; ++mi) {
            const int m  = m0 + wm * 64 + mi * 16 + g;
            const int bb = m >> 10;
            const int s  = m & 1023;
#pragma unroll
            for (int ni = 0; ni < 4; ++ni) {
                const int gn  = n0 + wn * 32 + ni * 8 + t * 2;
                const int rem = gn & 1023;
                const int hh  = rem >> 6;
                const int dd  = rem & 63;
                const float2 bi = *(const float2*)(bias + gn);
                __half* base = dst + ((size_t)(bb * NH + hh) * SEQ + s) * HD + dd;
                *(uint32_t*)(base) = h2u(c[mi][ni][0] + bi.x, c[mi][ni][1] + bi.y);
                *(uint32_t*)(base + 8 * HD) = h2u(c[mi][ni][2] + bi.x, c[mi][ni][3] + bi.y);
            }
        }
    } else {
#pragma unroll
        for (int mi = 0; mi < 4; ++mi) {
            const int m  = m0 + wm * 64 + mi * 16 + g;
            const int bb = m >> 10;
            const int s  = m & 1023;
#pragma unroll
            for (int ni = 0; ni < 4; ++ni) {
                const int gn  = n0 + wn * 32 + ni * 8 + t * 2;
                const int rem = gn & 1023;
                const int hh  = rem >> 6;
                const int dd  = rem & 63;
                const float2 bi = *(const float2*)(bias + gn);
                __half* base = g_Vt + ((size_t)(bb * NH + hh) * HD + dd) * SEQ + s;
                base[0]       = __float2half(c[mi][ni][0] + bi.x);
                base[SEQ]     = __float2half(c[mi][ni][1] + bi.y);
                base[8]       = __float2half(c[mi][ni][2] + bi.x);
                base[SEQ + 8] = __float2half(c[mi][ni][3] + bi.y);
            }
        }
    }
}

// ===========================================================================
// Kernel 2: attention — R14 structure with ldmatrix fragment loads.
// ===========================================================================
#define AT_SMEM_B 72448

__global__ __launch_bounds__(256, 2) void attn_mma(
    const float* __restrict__ mask,
    float* __restrict__ out)
{
    extern __shared__ __align__(16) float sm2[];
    __half* Qh    = (__half*)sm2;             // [64][72]
    __half* Kh    = (__half*)(sm2 + 2304);    // [64][72] (Vth alias)
    __half* Vth   = Kh;
    __half* Eh    = (__half*)(sm2 + 4608);    // [128][72] (Ph alias [64][72])
    __half* Ph    = Eh;
    __half* QEh   = (__half*)(sm2 + 9216);    // [64][136]
    __half* KEh   = (__half*)(sm2 + 13568);   // [64][136]
    float*  corrs = sm2 + 17920;              // [64]
    float*  lsums = sm2 + 17984;              // [64]
    float*  maskS = sm2 + 18048;              // [64]

    const int tid  = threadIdx.x;
    const int lane = tid & 31, g = lane >> 2, t = lane & 3;
    const int wid  = tid >> 5;
    const int ms   = (wid & 3) * 16;          // 16-row strip
    const int nh   = (wid >> 2) * 32;         // n-half for PV
    const bool isA = (wid < 4);
    const int bh = blockIdx.y, b = bh >> 4, hh = bh & 15;
    const int l0 = blockIdx.x * 64;

    // ldmatrix lane components (mappings validated in QKV R16)
    const int la16 = lane & 15, lh = lane >> 4, l8 = (lane >> 3) & 1, l7 = lane & 7;
    const uint32_t qb = (uint32_t)__cvta_generic_to_shared(Qh);
    const uint32_t kb = (uint32_t)__cvta_generic_to_shared(Kh);
    const uint32_t eb = (uint32_t)__cvta_generic_to_shared(Eh);
    const uint32_t aoffA = (uint32_t)(((ms + la16) * 72) + lh * 8) * 2; // + ks*32B

    // ---- stage Q (raw fp16 copy) ----
    const __half* Qg = g_Qh + ((size_t)bh * SEQ + l0) * HD;
#pragma unroll
    for (int it = 0; it < 2; ++it) {
        const int cidx = tid + it * 256;
        const int row = cidx >> 3, c16 = cidx & 7;
        *(uint4*)&Qh[row * 72 + c16 * 8] = *(const uint4*)(Qg + row * 64 + c16 * 8);
    }

    float mrow0 = -CUDART_INF_F, mrow1 = -CUDART_INF_F;
    float lsum0 = 0.f, lsum1 = 0.f;
    float acc[4][4];
#pragma unroll
    for (int nt = 0; nt < 4; ++nt)
#pragma unroll
        for (int r = 0; r < 4; ++r) acc[nt][r] = 0.f;

    float S[8][4];
    const int ebase = isA ? ms : (48 - ms);   // band start col for QE / KE

    for (int r0 = 0; r0 < SEQ; r0 += 64) {
        const int gb_ = l0 - r0 + 960;

        __syncthreads();   // sync1: prior PV reads (Ph, Vth) done
        const __half* Kg = g_Kh + ((size_t)bh * SEQ + r0) * HD;
#pragma unroll
        for (int it = 0; it < 2; ++it) {
            const int cidx = tid + it * 256;
            const int row = cidx >> 3, c16 = cidx & 7;
            *(uint4*)&Kh[row * 72 + c16 * 8] = *(const uint4*)(Kg + row * 64 + c16 * 8);
        }
#pragma unroll
        for (int it = 0; it < 4; ++it) {
            const int cidx = tid + it * 256;
            const int row = cidx >> 3, c16 = cidx & 7;
            const int er = min(gb_ + row, 2046);
            *(uint4*)&Eh[row * 72 + c16 * 8] = *(const uint4*)(emb_h + er * 64 + c16 * 8);
        }
        if (tid < 16)
            *(float4*)&maskS[tid * 4] = *(const float4*)(mask + b * SEQ + r0 + tid * 4);
        __syncthreads();   // sync2: operands ready

        // ---- fp16 band GEMM: QE (A warps) / KE (B warps), 10 n8 tiles ----
        {
            const uint32_t ab = isA ? qb : kb;
            __half* dstT = isA ? QEh : KEh;
#pragma unroll
            for (int c5 = 0; c5 < 2; ++c5) {
                const int cb0 = ebase + c5 * 40;
                float qe[5][4];
#pragma unroll
                for (int nt = 0; nt < 5; ++nt)
#pragma unroll
                    for (int r = 0; r < 4; ++r) qe[nt][r] = 0.f;
#pragma unroll
                for (int ks = 0; ks < 4; ++ks) {
                    uint32_t a[4];
                    ldsm4(a, ab + aoffA + ks * 32);
                    uint32_t bp[5][2];
#pragma unroll
                    for (int pp = 0; pp < 2; ++pp) {
                        uint32_t r[4];
                        ldsm4(r, eb + (uint32_t)(((cb0 + pp * 16 + lh * 8 + l7) * 72)
                                                 + ks * 16 + l8 * 8) * 2);
                        bp[2 * pp][0] = r[0]; bp[2 * pp][1] = r[1];
                        bp[2 * pp + 1][0] = r[2]; bp[2 * pp + 1][1] = r[3];
                    }
                    ldsm2(bp[4], eb + (uint32_t)(((cb0 + 32 + l7) * 72)
                                                 + ks * 16 + l8 * 8) * 2);
#pragma unroll
                    for (int nt = 0; nt < 5; ++nt)
                        mma16n8k16h(qe[nt], a, bp[nt]);
                }
#pragma unroll
                for (int nt = 0; nt < 5; ++nt) {
                    const int col = cb0 + nt * 8 + 2 * t;
                    *(__half2*)&dstT[(ms + g) * 136 + col] =
                        __floats2half2_rn(qe[nt][0], qe[nt][1]);
                    *(__half2*)&dstT[(ms + g + 8) * 136 + col] =
                        __floats2half2_rn(qe[nt][2], qe[nt][3]);
                }
            }
        }
        if (isA) {
            // ---- QK (fp16, ldmatrix) ----
#pragma unroll
            for (int nt = 0; nt < 8; ++nt)
#pragma unroll
                for (int r = 0; r < 4; ++r) S[nt][r] = 0.f;
#pragma unroll
            for (int ks = 0; ks < 4; ++ks) {
                uint32_t a[4];
                ldsm4(a, qb + aoffA + ks * 32);
#pragma unroll
                for (int pp = 0; pp < 4; ++pp) {
                    uint32_t r[4];
                    ldsm4(r, kb + (uint32_t)(((pp * 16 + lh * 8 + l7) * 72)
                                             + ks * 16 + l8 * 8) * 2);
                    uint32_t b0[2] = {r[0], r[1]}, b1[2] = {r[2], r[3]};
                    mma16n8k16h(S[2 * pp], a, b0);
                    mma16n8k16h(S[2 * pp + 1], a, b1);
                }
            }
        }
        __syncthreads();   // sync3: QEh/KEh done; Kh/Eh mma reads done

        if (isA) {
            // ---- gather + scale + mask + online softmax + P store (fp16) ----
            const int iA = ms + g, iB = ms + g + 8;
            float rmax0 = -CUDART_INF_F, rmax1 = -CUDART_INF_F;
#pragma unroll
            for (int nt = 0; nt < 8; ++nt) {
                const int j0 = nt * 8 + 2 * t, j1 = j0 + 1;
                const float mk0 = maskS[j0], mk1 = maskS[j1];
                const int bA0 = iA - j0 + 63, bA1 = iA - j1 + 63;
                const int bB0 = iB - j0 + 63, bB1 = iB - j1 + 63;
                S[nt][0] = (S[nt][0] + __half2float(QEh[iA * 136 + bA0])
                                     + __half2float(KEh[j0 * 136 + bA0])) * 0.125f + mk0;
                S[nt][1] = (S[nt][1] + __half2float(QEh[iA * 136 + bA1])
                                     + __half2float(KEh[j1 * 136 + bA1])) * 0.125f + mk1;
                S[nt][2] = (S[nt][2] + __half2float(QEh[iB * 136 + bB0])
                                     + __half2float(KEh[j0 * 136 + bB0])) * 0.125f + mk0;
                S[nt][3] = (S[nt][3] + __half2float(QEh[iB * 136 + bB1])
                                     + __half2float(KEh[j1 * 136 + bB1])) * 0.125f + mk1;
                rmax0 = fmaxf(rmax0, fmaxf(S[nt][0], S[nt][1]));
                rmax1 = fmaxf(rmax1, fmaxf(S[nt][2], S[nt][3]));
            }
            rmax0 = fmaxf(rmax0, __shfl_xor_sync(0xffffffffu, rmax0, 1));
            rmax0 = fmaxf(rmax0, __shfl_xor_sync(0xffffffffu, rmax0, 2));
            rmax1 = fmaxf(rmax1, __shfl_xor_sync(0xffffffffu, rmax1, 1));
            rmax1 = fmaxf(rmax1, __shfl_xor_sync(0xffffffffu, rmax1, 2));
            const float mn0 = fmaxf(mrow0, rmax0), mn1 = fmaxf(mrow1, rmax1);
            const float c0 = __expf(mrow0 - mn0), c1 = __expf(mrow1 - mn1);
            mrow0 = mn0; mrow1 = mn1;
            float ps0 = 0.f, ps1 = 0.f;
#pragma unroll
            for (int nt = 0; nt < 8; ++nt) {
                S[nt][0] = __expf(S[nt][0] - mn0); ps0 += S[nt][0];
                S[nt][1] = __expf(S[nt][1] - mn0); ps0 += S[nt][1];
                S[nt][2] = __expf(S[nt][2] - mn1); ps1 += S[nt][2];
                S[nt][3] = __expf(S[nt][3] - mn1); ps1 += S[nt][3];
            }
            ps0 += __shfl_xor_sync(0xffffffffu, ps0, 1);
            ps0 += __shfl_xor_sync(0xffffffffu, ps0, 2);
            ps1 += __shfl_xor_sync(0xffffffffu, ps1, 1);
            ps1 += __shfl_xor_sync(0xffffffffu, ps1, 2);
            lsum0 = lsum0 * c0 + ps0;
            lsum1 = lsum1 * c1 + ps1;
            if (t == 0) { corrs[iA] = c0; corrs[iB] = c1; }
#pragma unroll
            for (int nt = 0; nt < 8; ++nt) {
                const int col = nt * 8 + 2 * t;
                *(__half2*)&Ph[iA * 72 + col] = __floats2half2_rn(S[nt][0], S[nt][1]);
                *(__half2*)&Ph[iB * 72 + col] = __floats2half2_rn(S[nt][2], S[nt][3]);
            }
        } else {
            // ---- B warps: copy pre-transposed V tile ----
            const __half* Vg = g_Vt + (size_t)bh * HD * SEQ + r0;
            const int tl = tid - 128;
#pragma unroll
            for (int it = 0; it < 4; ++it) {
                const int cidx = tl + it * 128;
                const int dd = cidx >> 3, c16 = cidx & 7;
                *(uint4*)&Vth[dd * 72 + c16 * 8] =
                    *(const uint4*)(Vg + (size_t)dd * SEQ + c16 * 8);
            }
        }
        __syncthreads();   // sync4: Ph, Vth, corrs ready

        // ---- PV (fp16, ldmatrix): all warps ----
        {
            const float cc0 = corrs[ms + g], cc1 = corrs[ms + g + 8];
#pragma unroll
            for (int nt = 0; nt < 4; ++nt) {
                acc[nt][0] *= cc0; acc[nt][1] *= cc0;
                acc[nt][2] *= cc1; acc[nt][3] *= cc1;
            }
#pragma unroll
            for (int ks = 0; ks < 4; ++ks) {
                uint32_t a[4];
                ldsm4(a, eb + aoffA + ks * 32);   // Ph aliases Eh
#pragma unroll
                for (int pp = 0; pp < 2; ++pp) {
                    uint32_t r[4];
                    ldsm4(r, kb + (uint32_t)(((nh + pp * 16 + lh * 8 + l7) * 72)
                                             + ks * 16 + l8 * 8) * 2);  // Vth aliases Kh
                    uint32_t b0[2] = {r[0], r[1]}, b1[2] = {r[2], r[3]};
                    mma16n8k16h(acc[2 * pp], a, b0);
                    mma16n8k16h(acc[2 * pp + 1], a, b1);
                }
            }
        }
    }

    if (isA && t == 0) { lsums[ms + g] = lsum0; lsums[ms + g + 8] = lsum1; }
    __syncthreads();

    {
        const float inv0 = 1.f / lsums[ms + g];
        const float inv1 = 1.f / lsums[ms + g + 8];
        const int row0 = l0 + ms + g, row1 = row0 + 8;
#pragma unroll
        for (int nt = 0; nt < 4; ++nt) {
            const int col = hh * HD + nh + nt * 8 + 2 * t;
            *(float2*)(out + (size_t)(b * SEQ + row0) * HID + col) =
                make_float2(acc[nt][0] * inv0, acc[nt][1] * inv0);
            *(float2*)(out + (size_t)(b * SEQ + row1) * HID + col) =
                make_float2(acc[nt][2] * inv1, acc[nt][3] * inv1);
        }
    }
}

// ---------------------------------------------------------------------------
extern "C" void kernel_launch(void* const* d_in, const int* in_sizes, int n_in,
                              void* d_out, int out_size)
{
    (void)in_sizes; (void)n_in; (void)out_size;
    const float* hs   = (const float*)d_in[0];
    const float* w    = (const float*)d_in[1];
    const float* bias = (const float*)d_in[2];
    const float* emb  = (const float*)d_in[3];
    const float* mask = (const float*)d_in[4];
    float* out = (float*)d_out;

    const int total_q = HSQ + WQ + EQ;
    cvt_all<<<(total_q + 255) / 256, 256>>>(hs, w, emb);

    cudaFuncSetAttribute(qkv_gemm_mma,
                         cudaFuncAttributeMaxDynamicSharedMemorySize, QG_SMEM_B);
    qkv_gemm_mma<<<dim3(HID * 3 / 128, BATCH * SEQ / 128), 256, QG_SMEM_B>>>(bias);

    cudaFuncSetAttribute(attn_mma,
                         cudaFuncAttributeMaxDynamicSharedMemorySize, AT_SMEM_B);
    attn_mma<<<dim3(SEQ / 64, BATCH * NH), 256, AT_SMEM_B>>>(mask, out);
}